// round 15
// baseline (speedup 1.0000x reference)
#include <cuda_runtime.h>
#include <cuda_fp16.h>
#include <math.h>
#include <stdint.h>

// image 2048x2048 -> DWT high (stride-2, 2x2) -> 1024x1024
// pad to 1449x1449 with pad_before=212, center=724
// out[x*64 + t] = (sum_y bilinear(padded, rot_t(x,y))) / global_max, x<1448
#define MDIM  2048
#define HN    1024
#define PDIM  1449
#define PB    212
#define OUTW  1448
#define NA    64
#define CENTERF 724.0f

// rotsum touches quad indices only in [208,1240]^2; prep covers [200,1248)^2.
#define RLO   200
#define QSPAN 1048

__device__ uint2 g_h4[PDIM * PDIM];    // fp16 quad, column pairs: (v00,v10 | v01,v11)
__device__ unsigned g_maxkey;

#define PACK_F32X2(out, lo, hi) \
    asm("mov.b64 %0, {%1, %2};" : "=l"(out) : "f"(lo), "f"(hi))
#define UNPACK_F32X2(lo, hi, in) \
    asm("mov.b64 {%0, %1}, %2;" : "=f"(lo), "=f"(hi) : "l"(in))
#define FMA_F32X2(out, a, b, c) \
    asm("fma.rn.f32x2 %0, %1, %2, %3;" : "=l"(out) : "l"(a), "l"(b), "l"(c))
#define ADD_F32X2(out, a, b) \
    asm("add.rn.f32x2 %0, %1, %2;" : "=l"(out) : "l"(a), "l"(b))

// ---------------------------------------------------------------------------
// DWT high-pass value at (iy, ix); zero outside [0,1024)^2.
// ---------------------------------------------------------------------------
__device__ __forceinline__ float dwt_at(const float* __restrict__ img,
                                        int iy, int ix) {
    if ((unsigned)iy >= (unsigned)HN || (unsigned)ix >= (unsigned)HN) return 0.0f;
    const float2* r0 = (const float2*)(img + (size_t)(2 * iy) * MDIM) + ix;
    float2 a = __ldg(r0);
    float2 b = __ldg((const float2*)((const float*)r0 + MDIM));
    return -0.1384f * a.x + 0.7243f * a.y
           - 0.6038f * b.x + 0.1601f * b.y;
}

// ---------------------------------------------------------------------------
// Fused prep: compute the 2x2 DWT corner quad directly from img, pack fp16
// column pairs: q.x = (v00, v10), q.y = (v01, v11). Also resets max key.
// ---------------------------------------------------------------------------
__global__ void prep_kernel(const float* __restrict__ img) {
    int px = RLO + blockIdx.x * 32 + threadIdx.x;
    int py = RLO + blockIdx.y * 8 + threadIdx.y;
    if (blockIdx.x == 0 && blockIdx.y == 0 && threadIdx.x == 0 && threadIdx.y == 0)
        g_maxkey = 0u;
    if (px >= RLO + QSPAN || py >= RLO + QSPAN) return;
    int iy = py - PB;
    int ix = px - PB;
    float v00 = dwt_at(img, iy,     ix);
    float v01 = dwt_at(img, iy,     ix + 1);
    float v10 = dwt_at(img, iy + 1, ix);
    float v11 = dwt_at(img, iy + 1, ix + 1);
    __half2 c0 = __floats2half2_rn(v00, v10);
    __half2 c1 = __floats2half2_rn(v01, v11);
    uint2 q;
    q.x = *(unsigned*)&c0;
    q.y = *(unsigned*)&c1;
    g_h4[py * PDIM + px] = q;
}

__device__ __forceinline__ unsigned float_key(float f) {
    unsigned u = __float_as_uint(f);
    return (u & 0x80000000u) ? ~u : (u | 0x80000000u);
}

// ---------------------------------------------------------------------------
// For u(Y) = a*Y + b, compute Y-intervals (widened +-2, clamped to [0,1447])
// where floor(u) falls in the nonzero window [211,1235] + 1449*(k-1), k=0,1,2.
// ---------------------------------------------------------------------------
__device__ __forceinline__ void window_intervals(float a, float b,
                                                 float* lo, float* hi) {
    const float ra = 1.0f / a;
    #pragma unroll
    for (int k = 0; k < 3; k++) {
        float wlo = 211.0f + 1449.0f * (float)(k - 1);
        float whi = 1236.0f + 1449.0f * (float)(k - 1);
        if (fabsf(a) < 1e-5f) {
            bool in = (b >= wlo - 2.0f) && (b < whi + 2.0f);
            lo[k] = in ? 0.0f : 1e9f;
            hi[k] = in ? 1447.0f : -1e9f;
        } else {
            float y0 = (wlo - b) * ra;
            float y1 = (whi - b) * ra;
            if (a < 0.0f) { float tmp = y0; y0 = y1; y1 = tmp; }
            lo[k] = fmaxf(y0 - 2.0f, 0.0f);
            hi[k] = fminf(y1 + 2.0f, 1447.0f);
        }
    }
}

// Interval-walking accumulator, y-stride 16 (phase in 0..15).
// Inner loop: packed f32x2 coord math, 1 LDG.64, half2 x-lerp, fp32 y-lerp.
__device__ __forceinline__ float accum_intervals(float s, float c,
                                                 float cxk, float syk,
                                                 int phase) {
    float xlo[3], xhi[3], ylo[3], yhi[3];
    window_intervals(s, cxk, xlo, xhi);
    window_intervals(c, syk, ylo, yhi);

    uint64_t sc, basep, step16, neg1;
    PACK_F32X2(sc, s, c);
    PACK_F32X2(basep, cxk, syk);
    { float e = 16.0f; PACK_F32X2(step16, e, e); }
    { float m = -1.0f; PACK_F32X2(neg1, m, m); }

    float acc = 0.0f;
    #pragma unroll
    for (int kx = 0; kx < 3; kx++) {
        #pragma unroll
        for (int ky = 0; ky < 3; ky++) {
            float flo = fmaxf(xlo[kx], ylo[ky]);
            float fhi = fminf(xhi[kx], yhi[ky]);
            if (flo > fhi) continue;
            const int OFFC = -(ky - 1) * 1449 * PDIM - (kx - 1) * 1449;
            int yls = (int)ceilf(flo);
            yls += (phase - yls) & 15;           // align to y == phase (mod 16)
            const int yle = (int)floorf(fhi);
            if (yls > yle) continue;
            const int n = (yle - yls) >> 4;      // iterations - 1
            uint64_t Yp;
            { float Yf = (float)yls; PACK_F32X2(Yp, Yf, Yf); }
            const uint2* __restrict__ bp = g_h4 + OFFC;
            #pragma unroll 8
            for (int i = 0; i <= n; i++) {
                uint64_t fxy, dxy, ifp;
                FMA_F32X2(fxy, sc, Yp, basep);      // (fx, fy)
                float fx, fy;
                UNPACK_F32X2(fx, fy, fxy);
                int xi = __float2int_rd(fx);
                int yi = __float2int_rd(fy);
                float xf = (float)xi, yf = (float)yi;
                PACK_F32X2(ifp, xf, yf);
                FMA_F32X2(dxy, ifp, neg1, fxy);     // (dx, dy)
                float dx, dy;
                UNPACK_F32X2(dx, dy, dxy);
                ADD_F32X2(Yp, Yp, step16);
                uint2 q = __ldg(bp + yi * PDIM + xi);
                __half2 q0 = *(__half2*)&q.x;            // (v00, v10)
                __half2 q1 = *(__half2*)&q.y;            // (v01, v11)
                __half2 tb = __hfma2(__float2half2_rn(dx),
                                     __hsub2(q1, q0), q0);  // (top, bot)
                float2 tf = __half22float2(tb);
                acc += fmaf(dy, tf.y - tf.x, tf.x);
            }
        }
    }
    return acc;
}

// ---------------------------------------------------------------------------
// Rotsum: 512 threads = 32 output columns x 16 Y-phases. Warp lane micro-tile
// shape (la x lb, la*lb=32) chosen per angle by line-cost model.
// ---------------------------------------------------------------------------
__global__ void __launch_bounds__(512) rotsum_kernel(float* __restrict__ out) {
    const int t = blockIdx.y;
    float s, c;
    sincosf((float)t, &s, &c);
    const float as = fabsf(s), ac = fabsf(c);

    // pick lashift in {1..5} minimizing line-cost (block-uniform)
    float best = 1e30f;
    int lashift = 3;
    #pragma unroll
    for (int k = 1; k <= 5; k++) {
        float laf = (float)(1 << k);
        float lbf = (float)(32 >> k);
        float rows  = laf * as + lbf * ac + 1.0f;
        float xbyte = (laf * ac + lbf * as) * 8.0f + 96.0f;
        float cost = rows * xbyte;
        if (cost < best) { best = cost; lashift = k; }
    }
    const int la = 1 << lashift;
    const int lb = 32 >> lashift;            // lanes along phase
    const int wa = 32 >> lashift;            // warps along X
    const int washift = 5 - lashift;

    const int tid  = threadIdx.x;
    const int lane = tid & 31;
    const int w    = tid >> 5;               // 16 warps

    const int col   = ((w & (wa - 1)) << lashift) + (lane & (la - 1));
    const int phase = ((w >> washift) * lb) + (lane >> lashift);   // 0..15

    const int x = blockIdx.x * 32 + col;
    const float kx = CENTERF * (c + s - 1.0f);
    const float ky = CENTERF * (c - s - 1.0f);
    const float X = (float)x;
    const float cxk = fmaf(c, X, -kx);   // x_in = s*Y + cxk
    const float syk = fmaf(-s, X, -ky);  // y_in = c*Y + syk

    float acc = accum_intervals(s, c, cxk, syk, phase);

    __shared__ float sm[16][33];
    sm[phase][col] = acc;
    __syncthreads();

    if (tid < 32) {
        float v = sm[0][tid];
        #pragma unroll
        for (int p = 1; p < 16; p++) v += sm[p][tid];
        int xo = blockIdx.x * 32 + tid;
        float vm = v;
        if (xo < OUTW) out[(size_t)xo * NA + t] = v; else vm = -INFINITY;
        unsigned key = float_key(vm);
        #pragma unroll
        for (int o = 16; o > 0; o >>= 1) {
            unsigned other = __shfl_xor_sync(0xffffffffu, key, o);
            key = key > other ? key : other;
        }
        if (tid == 0) atomicMax(&g_maxkey, key);
    }
}

// ---------------------------------------------------------------------------
// Vectorized normalize: out_size = 1448*64 floats = 23168 float4 (divisible).
// ---------------------------------------------------------------------------
__global__ void norm_kernel(float4* __restrict__ out, int n4) {
    int i = blockIdx.x * blockDim.x + threadIdx.x;
    unsigned key = g_maxkey;
    unsigned u = (key & 0x80000000u) ? (key ^ 0x80000000u) : ~key;
    float rm = 1.0f;
    float m = __uint_as_float(u);
    rm = m;
    if (i < n4) {
        float4 v = out[i];
        v.x /= rm; v.y /= rm; v.z /= rm; v.w /= rm;
        out[i] = v;
    }
}

// ---------------------------------------------------------------------------
extern "C" void kernel_launch(void* const* d_in, const int* in_sizes, int n_in,
                              void* d_out, int out_size) {
    const float* img = (const float*)d_in[0];
    float* out = (float*)d_out;

    dim3 pb(32, 8);
    dim3 pg((QSPAN + 31) / 32, (QSPAN + 7) / 8);
    prep_kernel<<<pg, pb>>>(img);

    dim3 grid((OUTW + 31) / 32, NA);
    rotsum_kernel<<<grid, 512>>>(out);

    int n4 = out_size / 4;                   // 92672 / 4 = 23168, exact
    norm_kernel<<<(n4 + 255) / 256, 256>>>((float4*)out, n4);
}

// round 16
// speedup vs baseline: 1.0016x; 1.0016x over previous
#include <cuda_runtime.h>
#include <cuda_fp16.h>
#include <math.h>
#include <stdint.h>

// image 2048x2048 -> DWT high (stride-2, 2x2) -> 1024x1024
// pad to 1449x1449 with pad_before=212, center=724
// out[x*64 + t] = (sum_y bilinear(padded, rot_t(x,y))) / global_max, x<1448
#define MDIM  2048
#define HN    1024
#define PDIM  1449
#define PB    212
#define OUTW  1448
#define NA    64
#define CENTERF 724.0f

// rotsum touches quad indices only in [208,1240]^2; prep covers [200,1248)^2.
#define RLO   200
#define QSPAN 1048

__device__ uint2 g_h4[PDIM * PDIM];    // fp16 quad, column pairs: (v00,v10 | v01,v11)
__device__ unsigned g_maxkey;

#define PACK_F32X2(out, lo, hi) \
    asm("mov.b64 %0, {%1, %2};" : "=l"(out) : "f"(lo), "f"(hi))
#define UNPACK_F32X2(lo, hi, in) \
    asm("mov.b64 {%0, %1}, %2;" : "=f"(lo), "=f"(hi) : "l"(in))
#define FMA_F32X2(out, a, b, c) \
    asm("fma.rn.f32x2 %0, %1, %2, %3;" : "=l"(out) : "l"(a), "l"(b), "l"(c))
#define ADD_F32X2(out, a, b) \
    asm("add.rn.f32x2 %0, %1, %2;" : "=l"(out) : "l"(a), "l"(b))

// ---------------------------------------------------------------------------
// DWT high-pass value at (iy, ix); zero outside [0,1024)^2.
// ---------------------------------------------------------------------------
__device__ __forceinline__ float dwt_at(const float* __restrict__ img,
                                        int iy, int ix) {
    if ((unsigned)iy >= (unsigned)HN || (unsigned)ix >= (unsigned)HN) return 0.0f;
    const float2* r0 = (const float2*)(img + (size_t)(2 * iy) * MDIM) + ix;
    float2 a = __ldg(r0);
    float2 b = __ldg((const float2*)((const float*)r0 + MDIM));
    return -0.1384f * a.x + 0.7243f * a.y
           - 0.6038f * b.x + 0.1601f * b.y;
}

// ---------------------------------------------------------------------------
// Fused prep with SMEM dwt sharing. Block 32x8 outputs needs 33x9 = 297
// distinct DWT values; compute each once (<=2 per thread, independent),
// then assemble fp16 column-pair quads from smem.
// ---------------------------------------------------------------------------
__global__ void prep_kernel(const float* __restrict__ img) {
    __shared__ float sdw[9][33];
    const int tx = threadIdx.x;     // 0..31
    const int ty = threadIdx.y;     // 0..7
    const int tl = ty * 32 + tx;    // 0..255
    const int px0 = RLO + blockIdx.x * 32;
    const int py0 = RLO + blockIdx.y * 8;

    if (blockIdx.x == 0 && blockIdx.y == 0 && tl == 0) g_maxkey = 0u;

    // compute the 297 shared DWT values (each thread does 1-2)
    #pragma unroll
    for (int k = 0; k < 2; k++) {
        int j = tl + k * 256;
        if (j < 297) {
            int vy = j / 33;
            int vx = j - vy * 33;
            sdw[vy][vx] = dwt_at(img, py0 + vy - PB, px0 + vx - PB);
        }
    }
    __syncthreads();

    int px = px0 + tx;
    int py = py0 + ty;
    if (px >= RLO + QSPAN || py >= RLO + QSPAN) return;
    float v00 = sdw[ty][tx];
    float v01 = sdw[ty][tx + 1];
    float v10 = sdw[ty + 1][tx];
    float v11 = sdw[ty + 1][tx + 1];
    __half2 c0 = __floats2half2_rn(v00, v10);
    __half2 c1 = __floats2half2_rn(v01, v11);
    uint2 q;
    q.x = *(unsigned*)&c0;
    q.y = *(unsigned*)&c1;
    g_h4[py * PDIM + px] = q;
}

__device__ __forceinline__ unsigned float_key(float f) {
    unsigned u = __float_as_uint(f);
    return (u & 0x80000000u) ? ~u : (u | 0x80000000u);
}

// ---------------------------------------------------------------------------
// For u(Y) = a*Y + b, compute Y-intervals (widened +-2, clamped to [0,1447])
// where floor(u) falls in the nonzero window [211,1235] + 1449*(k-1), k=0,1,2.
// ---------------------------------------------------------------------------
__device__ __forceinline__ void window_intervals(float a, float b,
                                                 float* lo, float* hi) {
    const float ra = 1.0f / a;
    #pragma unroll
    for (int k = 0; k < 3; k++) {
        float wlo = 211.0f + 1449.0f * (float)(k - 1);
        float whi = 1236.0f + 1449.0f * (float)(k - 1);
        if (fabsf(a) < 1e-5f) {
            bool in = (b >= wlo - 2.0f) && (b < whi + 2.0f);
            lo[k] = in ? 0.0f : 1e9f;
            hi[k] = in ? 1447.0f : -1e9f;
        } else {
            float y0 = (wlo - b) * ra;
            float y1 = (whi - b) * ra;
            if (a < 0.0f) { float tmp = y0; y0 = y1; y1 = tmp; }
            lo[k] = fmaxf(y0 - 2.0f, 0.0f);
            hi[k] = fminf(y1 + 2.0f, 1447.0f);
        }
    }
}

// Interval-walking accumulator, y-stride 16 (phase in 0..15).
// Inner loop: packed f32x2 coord math, 1 LDG.64, half2 x-lerp, fp32 y-lerp.
__device__ __forceinline__ float accum_intervals(float s, float c,
                                                 float cxk, float syk,
                                                 int phase) {
    float xlo[3], xhi[3], ylo[3], yhi[3];
    window_intervals(s, cxk, xlo, xhi);
    window_intervals(c, syk, ylo, yhi);

    uint64_t sc, basep, step16, neg1;
    PACK_F32X2(sc, s, c);
    PACK_F32X2(basep, cxk, syk);
    { float e = 16.0f; PACK_F32X2(step16, e, e); }
    { float m = -1.0f; PACK_F32X2(neg1, m, m); }

    float acc = 0.0f;
    #pragma unroll
    for (int kx = 0; kx < 3; kx++) {
        #pragma unroll
        for (int ky = 0; ky < 3; ky++) {
            float flo = fmaxf(xlo[kx], ylo[ky]);
            float fhi = fminf(xhi[kx], yhi[ky]);
            if (flo > fhi) continue;
            const int OFFC = -(ky - 1) * 1449 * PDIM - (kx - 1) * 1449;
            int yls = (int)ceilf(flo);
            yls += (phase - yls) & 15;           // align to y == phase (mod 16)
            const int yle = (int)floorf(fhi);
            if (yls > yle) continue;
            const int n = (yle - yls) >> 4;      // iterations - 1
            uint64_t Yp;
            { float Yf = (float)yls; PACK_F32X2(Yp, Yf, Yf); }
            const uint2* __restrict__ bp = g_h4 + OFFC;
            #pragma unroll 4
            for (int i = 0; i <= n; i++) {
                uint64_t fxy, dxy, ifp;
                FMA_F32X2(fxy, sc, Yp, basep);      // (fx, fy)
                float fx, fy;
                UNPACK_F32X2(fx, fy, fxy);
                int xi = __float2int_rd(fx);
                int yi = __float2int_rd(fy);
                float xf = (float)xi, yf = (float)yi;
                PACK_F32X2(ifp, xf, yf);
                FMA_F32X2(dxy, ifp, neg1, fxy);     // (dx, dy)
                float dx, dy;
                UNPACK_F32X2(dx, dy, dxy);
                ADD_F32X2(Yp, Yp, step16);
                uint2 q = __ldg(bp + yi * PDIM + xi);
                __half2 q0 = *(__half2*)&q.x;            // (v00, v10)
                __half2 q1 = *(__half2*)&q.y;            // (v01, v11)
                __half2 tb = __hfma2(__float2half2_rn(dx),
                                     __hsub2(q1, q0), q0);  // (top, bot)
                float2 tf = __half22float2(tb);
                acc += fmaf(dy, tf.y - tf.x, tf.x);
            }
        }
    }
    return acc;
}

// ---------------------------------------------------------------------------
// Rotsum: 512 threads = 32 output columns x 16 Y-phases. Warp lane micro-tile
// shape (la x lb, la*lb=32) chosen per angle by line-cost model.
// ---------------------------------------------------------------------------
__global__ void __launch_bounds__(512) rotsum_kernel(float* __restrict__ out) {
    const int t = blockIdx.y;
    float s, c;
    sincosf((float)t, &s, &c);
    const float as = fabsf(s), ac = fabsf(c);

    // pick lashift in {1..5} minimizing line-cost (block-uniform)
    float best = 1e30f;
    int lashift = 3;
    #pragma unroll
    for (int k = 1; k <= 5; k++) {
        float laf = (float)(1 << k);
        float lbf = (float)(32 >> k);
        float rows  = laf * as + lbf * ac + 1.0f;
        float xbyte = (laf * ac + lbf * as) * 8.0f + 96.0f;
        float cost = rows * xbyte;
        if (cost < best) { best = cost; lashift = k; }
    }
    const int la = 1 << lashift;
    const int lb = 32 >> lashift;            // lanes along phase
    const int wa = 32 >> lashift;            // warps along X
    const int washift = 5 - lashift;

    const int tid  = threadIdx.x;
    const int lane = tid & 31;
    const int w    = tid >> 5;               // 16 warps

    const int col   = ((w & (wa - 1)) << lashift) + (lane & (la - 1));
    const int phase = ((w >> washift) * lb) + (lane >> lashift);   // 0..15

    const int x = blockIdx.x * 32 + col;
    const float kx = CENTERF * (c + s - 1.0f);
    const float ky = CENTERF * (c - s - 1.0f);
    const float X = (float)x;
    const float cxk = fmaf(c, X, -kx);   // x_in = s*Y + cxk
    const float syk = fmaf(-s, X, -ky);  // y_in = c*Y + syk

    float acc = accum_intervals(s, c, cxk, syk, phase);

    __shared__ float sm[16][33];
    sm[phase][col] = acc;
    __syncthreads();

    if (tid < 32) {
        float v = sm[0][tid];
        #pragma unroll
        for (int p = 1; p < 16; p++) v += sm[p][tid];
        int xo = blockIdx.x * 32 + tid;
        float vm = v;
        if (xo < OUTW) out[(size_t)xo * NA + t] = v; else vm = -INFINITY;
        unsigned key = float_key(vm);
        #pragma unroll
        for (int o = 16; o > 0; o >>= 1) {
            unsigned other = __shfl_xor_sync(0xffffffffu, key, o);
            key = key > other ? key : other;
        }
        if (tid == 0) atomicMax(&g_maxkey, key);
    }
}

// ---------------------------------------------------------------------------
// Vectorized normalize: one divide per thread, 4 multiplies.
// out_size = 1448*64 = 92672 floats = 23168 float4 (exact).
// ---------------------------------------------------------------------------
__global__ void norm_kernel(float4* __restrict__ out, int n4) {
    int i = blockIdx.x * blockDim.x + threadIdx.x;
    unsigned key = g_maxkey;
    unsigned u = (key & 0x80000000u) ? (key ^ 0x80000000u) : ~key;
    float m = __uint_as_float(u);
    float rm = 1.0f / m;
    if (i < n4) {
        float4 v = out[i];
        v.x *= rm; v.y *= rm; v.z *= rm; v.w *= rm;
        out[i] = v;
    }
}

// ---------------------------------------------------------------------------
extern "C" void kernel_launch(void* const* d_in, const int* in_sizes, int n_in,
                              void* d_out, int out_size) {
    const float* img = (const float*)d_in[0];
    float* out = (float*)d_out;

    dim3 pb(32, 8);
    dim3 pg((QSPAN + 31) / 32, (QSPAN + 7) / 8);
    prep_kernel<<<pg, pb>>>(img);

    dim3 grid((OUTW + 31) / 32, NA);
    rotsum_kernel<<<grid, 512>>>(out);

    int n4 = out_size / 4;                   // 23168, exact
    norm_kernel<<<(n4 + 255) / 256, 256>>>((float4*)out, n4);
}

// round 17
// speedup vs baseline: 1.0206x; 1.0189x over previous
#include <cuda_runtime.h>
#include <cuda_fp16.h>
#include <math.h>
#include <stdint.h>

// image 2048x2048 -> DWT high (stride-2, 2x2) -> 1024x1024
// pad to 1449x1449 with pad_before=212, center=724
// out[x*64 + t] = (sum_y bilinear(padded, rot_t(x,y))) / global_max, x<1448
#define MDIM  2048
#define HN    1024
#define PDIM  1449
#define PB    212
#define OUTW  1448
#define NA    64
#define CENTERF 724.0f

// rotsum touches quad indices only in [208,1240]^2; prep covers [200,1248)^2.
#define RLO   200
#define QSPAN 1048

__device__ uint2 g_h4[PDIM * PDIM];    // fp16 quad, column pairs: (v00,v10 | v01,v11)
__device__ unsigned g_maxkey;

#define PACK_F32X2(out, lo, hi) \
    asm("mov.b64 %0, {%1, %2};" : "=l"(out) : "f"(lo), "f"(hi))
#define UNPACK_F32X2(lo, hi, in) \
    asm("mov.b64 {%0, %1}, %2;" : "=f"(lo), "=f"(hi) : "l"(in))
#define FMA_F32X2(out, a, b, c) \
    asm("fma.rn.f32x2 %0, %1, %2, %3;" : "=l"(out) : "l"(a), "l"(b), "l"(c))
#define ADD_F32X2(out, a, b) \
    asm("add.rn.f32x2 %0, %1, %2;" : "=l"(out) : "l"(a), "l"(b))

__device__ __forceinline__ float dwt_comb(float a0, float a1, float b0, float b1) {
    return -0.1384f * a0 + 0.7243f * a1 - 0.6038f * b0 + 0.1601f * b1;
}

// DWT high-pass value at (iy, ix); zero outside [0,1024)^2. (slow/edge path)
__device__ __forceinline__ float dwt_at(const float* __restrict__ img,
                                        int iy, int ix) {
    if ((unsigned)iy >= (unsigned)HN || (unsigned)ix >= (unsigned)HN) return 0.0f;
    const float2* r0 = (const float2*)(img + (size_t)(2 * iy) * MDIM) + ix;
    float2 a = __ldg(r0);
    float2 b = __ldg((const float2*)((const float*)r0 + MDIM));
    return dwt_comb(a.x, a.y, b.x, b.y);
}

// ---------------------------------------------------------------------------
// Fused prep, 2 quads per thread (px even). Interior: 8x LDG.128 covering
// img rows 2iy..2iy+3, cols 2ix..2ix+7 -> dwt values d[2][3] -> 2 quads.
// Edge threads use the guarded per-corner path. Bit-identical values.
// ---------------------------------------------------------------------------
__global__ void prep_kernel(const float* __restrict__ img) {
    const int tx = threadIdx.x;     // 0..31
    const int ty = threadIdx.y;     // 0..7
    int px = RLO + blockIdx.x * 64 + tx * 2;    // even (RLO even)
    int py = RLO + blockIdx.y * 8 + ty;
    if (blockIdx.x == 0 && blockIdx.y == 0 && tx == 0 && ty == 0)
        g_maxkey = 0u;
    if (px >= RLO + QSPAN || py >= RLO + QSPAN) return;
    int ix = px - PB;               // even
    int iy = py - PB;

    float d[2][3];
    bool interior = ((unsigned)iy <= (unsigned)(HN - 2)) &&
                    ((unsigned)ix <= (unsigned)(HN - 4));
    if (interior) {
        float4 ra[4], rb[4];
        #pragma unroll
        for (int r = 0; r < 4; r++) {
            const float4* rp = (const float4*)(img + (size_t)(2 * iy + r) * MDIM + 2 * ix);
            ra[r] = __ldg(rp);
            rb[r] = __ldg(rp + 1);
        }
        #pragma unroll
        for (int ry = 0; ry < 2; ry++) {
            const float4 t0 = ra[2 * ry],     t1 = rb[2 * ry];
            const float4 u0 = ra[2 * ry + 1], u1 = rb[2 * ry + 1];
            d[ry][0] = dwt_comb(t0.x, t0.y, u0.x, u0.y);
            d[ry][1] = dwt_comb(t0.z, t0.w, u0.z, u0.w);
            d[ry][2] = dwt_comb(t1.x, t1.y, u1.x, u1.y);
        }
    } else {
        #pragma unroll
        for (int ry = 0; ry < 2; ry++)
            #pragma unroll
            for (int cx = 0; cx < 3; cx++)
                d[ry][cx] = dwt_at(img, iy + ry, ix + cx);
    }

    __half2 c0 = __floats2half2_rn(d[0][0], d[1][0]);
    __half2 c1 = __floats2half2_rn(d[0][1], d[1][1]);
    __half2 c2 = __floats2half2_rn(d[0][2], d[1][2]);
    uint2 q0, q1;
    q0.x = *(unsigned*)&c0;  q0.y = *(unsigned*)&c1;   // quad at px
    q1.x = *(unsigned*)&c1;  q1.y = *(unsigned*)&c2;   // quad at px+1
    int base = py * PDIM + px;
    g_h4[base] = q0;
    g_h4[base + 1] = q1;
}

__device__ __forceinline__ unsigned float_key(float f) {
    unsigned u = __float_as_uint(f);
    return (u & 0x80000000u) ? ~u : (u | 0x80000000u);
}

// ---------------------------------------------------------------------------
// For u(Y) = a*Y + b, compute Y-intervals (widened +-2, clamped to [0,1447])
// where floor(u) falls in the nonzero window [211,1235] + 1449*(k-1), k=0,1,2.
// ---------------------------------------------------------------------------
__device__ __forceinline__ void window_intervals(float a, float b,
                                                 float* lo, float* hi) {
    const float ra = 1.0f / a;
    #pragma unroll
    for (int k = 0; k < 3; k++) {
        float wlo = 211.0f + 1449.0f * (float)(k - 1);
        float whi = 1236.0f + 1449.0f * (float)(k - 1);
        if (fabsf(a) < 1e-5f) {
            bool in = (b >= wlo - 2.0f) && (b < whi + 2.0f);
            lo[k] = in ? 0.0f : 1e9f;
            hi[k] = in ? 1447.0f : -1e9f;
        } else {
            float y0 = (wlo - b) * ra;
            float y1 = (whi - b) * ra;
            if (a < 0.0f) { float tmp = y0; y0 = y1; y1 = tmp; }
            lo[k] = fmaxf(y0 - 2.0f, 0.0f);
            hi[k] = fminf(y1 + 2.0f, 1447.0f);
        }
    }
}

// Interval-walking accumulator, y-stride 16 (phase in 0..15).
// Inner loop: packed f32x2 coord math, 1 LDG.64, half2 x-lerp, fp32 y-lerp.
__device__ __forceinline__ float accum_intervals(float s, float c,
                                                 float cxk, float syk,
                                                 int phase) {
    float xlo[3], xhi[3], ylo[3], yhi[3];
    window_intervals(s, cxk, xlo, xhi);
    window_intervals(c, syk, ylo, yhi);

    uint64_t sc, basep, step16, neg1;
    PACK_F32X2(sc, s, c);
    PACK_F32X2(basep, cxk, syk);
    { float e = 16.0f; PACK_F32X2(step16, e, e); }
    { float m = -1.0f; PACK_F32X2(neg1, m, m); }

    float acc = 0.0f;
    #pragma unroll
    for (int kx = 0; kx < 3; kx++) {
        #pragma unroll
        for (int ky = 0; ky < 3; ky++) {
            float flo = fmaxf(xlo[kx], ylo[ky]);
            float fhi = fminf(xhi[kx], yhi[ky]);
            if (flo > fhi) continue;
            const int OFFC = -(ky - 1) * 1449 * PDIM - (kx - 1) * 1449;
            int yls = (int)ceilf(flo);
            yls += (phase - yls) & 15;           // align to y == phase (mod 16)
            const int yle = (int)floorf(fhi);
            if (yls > yle) continue;
            const int n = (yle - yls) >> 4;      // iterations - 1
            uint64_t Yp;
            { float Yf = (float)yls; PACK_F32X2(Yp, Yf, Yf); }
            const uint2* __restrict__ bp = g_h4 + OFFC;
            #pragma unroll 4
            for (int i = 0; i <= n; i++) {
                uint64_t fxy, dxy, ifp;
                FMA_F32X2(fxy, sc, Yp, basep);      // (fx, fy)
                float fx, fy;
                UNPACK_F32X2(fx, fy, fxy);
                int xi = __float2int_rd(fx);
                int yi = __float2int_rd(fy);
                float xf = (float)xi, yf = (float)yi;
                PACK_F32X2(ifp, xf, yf);
                FMA_F32X2(dxy, ifp, neg1, fxy);     // (dx, dy)
                float dx, dy;
                UNPACK_F32X2(dx, dy, dxy);
                ADD_F32X2(Yp, Yp, step16);
                uint2 q = __ldg(bp + yi * PDIM + xi);
                __half2 q0 = *(__half2*)&q.x;            // (v00, v10)
                __half2 q1 = *(__half2*)&q.y;            // (v01, v11)
                __half2 tb = __hfma2(__float2half2_rn(dx),
                                     __hsub2(q1, q0), q0);  // (top, bot)
                float2 tf = __half22float2(tb);
                acc += fmaf(dy, tf.y - tf.x, tf.x);
            }
        }
    }
    return acc;
}

// ---------------------------------------------------------------------------
// Rotsum: 512 threads = 32 output columns x 16 Y-phases. Warp lane micro-tile
// shape (la x lb, la*lb=32) chosen per angle to minimize rows touched:
// rows ~= la*|s| + lb*|c|. Shapes: 16x2, 8x4, 4x8, 2x16.  (round-13 config)
// ---------------------------------------------------------------------------
__global__ void __launch_bounds__(512) rotsum_kernel(float* __restrict__ out) {
    const int t = blockIdx.y;
    float s, c;
    sincosf((float)t, &s, &c);
    const float as = fabsf(s), ac = fabsf(c);

    // pick la from {16,8,4,2} minimizing la*as + (32/la)*ac   (block-uniform)
    float best = 1e30f;
    int lashift = 3;
    #pragma unroll
    for (int k = 1; k <= 4; k++) {
        float laf = (float)(1 << k);
        float lbf = (float)(32 >> k);
        float cost = laf * as + lbf * ac;
        if (cost < best) { best = cost; lashift = k; }
    }
    const int la = 1 << lashift;
    const int lb = 32 >> lashift;            // lanes along phase
    const int wa = 32 >> lashift;            // warps along X
    const int washift = 5 - lashift;

    const int tid  = threadIdx.x;
    const int lane = tid & 31;
    const int w    = tid >> 5;               // 16 warps

    const int col   = ((w & (wa - 1)) << lashift) + (lane & (la - 1));
    const int phase = ((w >> washift) * lb) + (lane >> lashift);   // 0..15

    const int x = blockIdx.x * 32 + col;
    const float kx = CENTERF * (c + s - 1.0f);
    const float ky = CENTERF * (c - s - 1.0f);
    const float X = (float)x;
    const float cxk = fmaf(c, X, -kx);   // x_in = s*Y + cxk
    const float syk = fmaf(-s, X, -ky);  // y_in = c*Y + syk

    float acc = accum_intervals(s, c, cxk, syk, phase);

    __shared__ float sm[16][33];
    sm[phase][col] = acc;
    __syncthreads();

    if (tid < 32) {
        float v = sm[0][tid];
        #pragma unroll
        for (int p = 1; p < 16; p++) v += sm[p][tid];
        int xo = blockIdx.x * 32 + tid;
        float vm = v;
        if (xo < OUTW) out[(size_t)xo * NA + t] = v; else vm = -INFINITY;
        unsigned key = float_key(vm);
        #pragma unroll
        for (int o = 16; o > 0; o >>= 1) {
            unsigned other = __shfl_xor_sync(0xffffffffu, key, o);
            key = key > other ? key : other;
        }
        if (tid == 0) atomicMax(&g_maxkey, key);
    }
}

// ---------------------------------------------------------------------------
// Vectorized normalize: one divide per thread, 4 multiplies.
// out_size = 1448*64 = 92672 floats = 23168 float4 (exact).
// ---------------------------------------------------------------------------
__global__ void norm_kernel(float4* __restrict__ out, int n4) {
    int i = blockIdx.x * blockDim.x + threadIdx.x;
    unsigned key = g_maxkey;
    unsigned u = (key & 0x80000000u) ? (key ^ 0x80000000u) : ~key;
    float m = __uint_as_float(u);
    float rm = 1.0f / m;
    if (i < n4) {
        float4 v = out[i];
        v.x *= rm; v.y *= rm; v.z *= rm; v.w *= rm;
        out[i] = v;
    }
}

// ---------------------------------------------------------------------------
extern "C" void kernel_launch(void* const* d_in, const int* in_sizes, int n_in,
                              void* d_out, int out_size) {
    const float* img = (const float*)d_in[0];
    float* out = (float*)d_out;

    dim3 pb(32, 8);
    dim3 pg((QSPAN + 63) / 64, (QSPAN + 7) / 8);
    prep_kernel<<<pg, pb>>>(img);

    dim3 grid((OUTW + 31) / 32, NA);
    rotsum_kernel<<<grid, 512>>>(out);

    int n4 = out_size / 4;                   // 23168, exact
    norm_kernel<<<(n4 + 255) / 256, 256>>>((float4*)out, n4);
}